// round 6
// baseline (speedup 1.0000x reference)
#include <cuda_runtime.h>
#include <cuda_fp16.h>
#include <math.h>
#include <stdint.h>

#define BB 64      // batch
#define TT 512     // seq len
#define DD 512     // input size
#define HH 1024    // hidden size
#define GG 4096    // 4*H

// ---------------------------------------------------------------------------
// Global scratch
// ---------------------------------------------------------------------------
// xz permuted: [dir][t][b][p] with p = j*4 + g (gate-interleaved)
__device__ float g_xz[(size_t)2 * TT * BB * GG];
// Wh fp16 split, B-fragment order: [dir][mat][nt(512)][kc16(64)][lane(32)]
__device__ uint2 g_Wfrag[(size_t)2 * 2 * 512 * 64 * 32];
// Wx fp16 split, B-fragment order: [dir][mat][nt(512)][kc16(32)][lane(32)]
__device__ uint2 g_Wxfrag[(size_t)2 * 2 * 512 * 32 * 32];
// permuted bias per dir
__device__ float g_biasp[2 * GG];
// X fp16 split: [m(32768)][k(512)]
__device__ __half g_Xh[(size_t)32768 * 512];
__device__ __half g_Xl[(size_t)32768 * 512];
// h fp16 split: [parity][dir][mat][kc64(16)][b(64)][64 halfs = 128B]
__device__ __align__(16) char g_A[(size_t)2 * 2 * 2 * 16 * 64 * 128];
// global barrier counter (zeroed each replay by init_kernel)
__device__ unsigned g_barrier;

#define A_MAT ((size_t)16 * 64 * 128)   // 131072 B per (parity,dir,mat)

// ---------------------------------------------------------------------------
#define MMA16816(d, a0, a1, a2, a3, b0, b1)                                  \
    asm volatile(                                                            \
        "mma.sync.aligned.m16n8k16.row.col.f32.f16.f16.f32 "                 \
        "{%0,%1,%2,%3}, {%4,%5,%6,%7}, {%8,%9}, {%0,%1,%2,%3};"              \
        : "+f"((d)[0]), "+f"((d)[1]), "+f"((d)[2]), "+f"((d)[3])             \
        : "r"(a0), "r"(a1), "r"(a2), "r"(a3), "r"(b0), "r"(b1))

#define LDSM_X4(r0, r1, r2, r3, addr)                                        \
    asm volatile(                                                            \
        "ldmatrix.sync.aligned.m8n8.x4.shared.b16 {%0,%1,%2,%3}, [%4];"      \
        : "=r"(r0), "=r"(r1), "=r"(r2), "=r"(r3) : "r"(addr))

#define CP16(dst, src)                                                       \
    asm volatile("cp.async.cg.shared.global [%0], [%1], 16;"                 \
                 :: "r"(dst), "l"(src))

__device__ __forceinline__ uint32_t smem_u32(const void* p) {
    uint32_t a;
    asm("{ .reg .u64 t; cvta.to.shared.u64 t, %1; cvt.u32.u64 %0, t; }"
        : "=r"(a) : "l"(p));
    return a;
}

// ---------------------------------------------------------------------------
// Init: zero g_A and the barrier counter
// ---------------------------------------------------------------------------
__global__ void init_kernel() {
    int i = blockIdx.x * blockDim.x + threadIdx.x;   // 0..262143
    ((uint32_t*)g_A)[i] = 0u;
    if (i == 0) g_barrier = 0u;
}

// ---------------------------------------------------------------------------
// X fp32 -> fp16 hi/lo
// ---------------------------------------------------------------------------
__global__ void convX_kernel(const float* __restrict__ X) {
    size_t idx = (size_t)blockIdx.x * blockDim.x + threadIdx.x;  // < 4M
    float4 v = ((const float4*)X)[idx];
    __half h0 = __float2half_rn(v.x), h1 = __float2half_rn(v.y);
    __half h2 = __float2half_rn(v.z), h3 = __float2half_rn(v.w);
    uint2 hi, lo;
    hi.x = (uint32_t)__half_as_ushort(h0) | ((uint32_t)__half_as_ushort(h1) << 16);
    hi.y = (uint32_t)__half_as_ushort(h2) | ((uint32_t)__half_as_ushort(h3) << 16);
    __half l0 = __float2half_rn(v.x - __half2float(h0));
    __half l1 = __float2half_rn(v.y - __half2float(h1));
    __half l2 = __float2half_rn(v.z - __half2float(h2));
    __half l3 = __float2half_rn(v.w - __half2float(h3));
    lo.x = (uint32_t)__half_as_ushort(l0) | ((uint32_t)__half_as_ushort(l1) << 16);
    lo.y = (uint32_t)__half_as_ushort(l2) | ((uint32_t)__half_as_ushort(l3) << 16);
    ((uint2*)g_Xh)[idx] = hi;
    ((uint2*)g_Xl)[idx] = lo;
}

// ---------------------------------------------------------------------------
// Wh fp32 -> fp16 hi/lo B-fragment order (K=1024 -> 64 kc)
// ---------------------------------------------------------------------------
__global__ void convW_kernel(const float* __restrict__ Whf,
                             const float* __restrict__ Whb) {
    int idx = blockIdx.x * blockDim.x + threadIdx.x;   // 0 .. 2^21-1
    int lane = idx & 31;
    int kc   = (idx >> 5) & 63;
    int nt   = (idx >> 11) & 511;
    int dir  = idx >> 20;
    const float* W = dir ? Whb : Whf;

    int p   = nt * 8 + (lane >> 2);
    int col = ((p & 3) << 10) + (p >> 2);
    int k0  = kc * 16 + (lane & 3) * 2;

    float w0 = W[(size_t)(k0)     * GG + col];
    float w1 = W[(size_t)(k0 + 1) * GG + col];
    float w2 = W[(size_t)(k0 + 8) * GG + col];
    float w3 = W[(size_t)(k0 + 9) * GG + col];

    __half h0 = __float2half_rn(w0), h1 = __float2half_rn(w1);
    __half h2 = __float2half_rn(w2), h3 = __float2half_rn(w3);
    uint2 hi, lo;
    hi.x = (uint32_t)__half_as_ushort(h0) | ((uint32_t)__half_as_ushort(h1) << 16);
    hi.y = (uint32_t)__half_as_ushort(h2) | ((uint32_t)__half_as_ushort(h3) << 16);
    lo.x = (uint32_t)__half_as_ushort(__float2half_rn(w0 - __half2float(h0))) |
           ((uint32_t)__half_as_ushort(__float2half_rn(w1 - __half2float(h1))) << 16);
    lo.y = (uint32_t)__half_as_ushort(__float2half_rn(w2 - __half2float(h2))) |
           ((uint32_t)__half_as_ushort(__float2half_rn(w3 - __half2float(h3))) << 16);

    g_Wfrag[((((size_t)dir * 2 + 0) * 512 + nt) * 64 + kc) * 32 + lane] = hi;
    g_Wfrag[((((size_t)dir * 2 + 1) * 512 + nt) * 64 + kc) * 32 + lane] = lo;
}

// ---------------------------------------------------------------------------
// Wx fp32 -> fp16 hi/lo B-fragment order (K=512 -> 32 kc) + permuted bias
// ---------------------------------------------------------------------------
__global__ void convWx_kernel(const float* __restrict__ Wxf,
                              const float* __restrict__ Wxb,
                              const float* __restrict__ bf,
                              const float* __restrict__ bb) {
    int idx = blockIdx.x * blockDim.x + threadIdx.x;   // 0 .. 2^20-1
    int lane = idx & 31;
    int kc   = (idx >> 5) & 31;
    int nt   = (idx >> 10) & 511;
    int dir  = idx >> 19;
    const float* W = dir ? Wxb : Wxf;

    int p   = nt * 8 + (lane >> 2);
    int col = ((p & 3) << 10) + (p >> 2);
    int k0  = kc * 16 + (lane & 3) * 2;

    float w0 = W[(size_t)(k0)     * GG + col];
    float w1 = W[(size_t)(k0 + 1) * GG + col];
    float w2 = W[(size_t)(k0 + 8) * GG + col];
    float w3 = W[(size_t)(k0 + 9) * GG + col];

    __half h0 = __float2half_rn(w0), h1 = __float2half_rn(w1);
    __half h2 = __float2half_rn(w2), h3 = __float2half_rn(w3);
    uint2 hi, lo;
    hi.x = (uint32_t)__half_as_ushort(h0) | ((uint32_t)__half_as_ushort(h1) << 16);
    hi.y = (uint32_t)__half_as_ushort(h2) | ((uint32_t)__half_as_ushort(h3) << 16);
    lo.x = (uint32_t)__half_as_ushort(__float2half_rn(w0 - __half2float(h0))) |
           ((uint32_t)__half_as_ushort(__float2half_rn(w1 - __half2float(h1))) << 16);
    lo.y = (uint32_t)__half_as_ushort(__float2half_rn(w2 - __half2float(h2))) |
           ((uint32_t)__half_as_ushort(__float2half_rn(w3 - __half2float(h3))) << 16);

    g_Wxfrag[((((size_t)dir * 2 + 0) * 512 + nt) * 32 + kc) * 32 + lane] = hi;
    g_Wxfrag[((((size_t)dir * 2 + 1) * 512 + nt) * 32 + kc) * 32 + lane] = lo;

    if (kc == 0 && (lane & 3) == 0) {
        const float* bias = dir ? bb : bf;
        g_biasp[dir * GG + p] = bias[col];
    }
}

// ---------------------------------------------------------------------------
// Input projection: fp16 3-term split mma. CTA tile 128m x 128n (permuted).
// ---------------------------------------------------------------------------
__global__ void __launch_bounds__(256, 1) proj_kernel() {
    __shared__ __align__(16) char sX[2 * 12288];   // 2 buf x 2 mat x 128 x 48B

    const int dir = blockIdx.z;
    const int n0 = blockIdx.x * 128;
    const int m0 = blockIdx.y * 128;
    const int tid = threadIdx.x;
    const int warp = tid >> 5, lane = tid & 31;
    const int wm = warp >> 2, wn = warp & 3;
    const int qr = lane >> 2, qc = lane & 3;

    const size_t MATSTRIDE = (size_t)512 * 32 * 32;
    const uint2* WX = g_Wxfrag + (size_t)dir * 2 * MATSTRIDE;
    const int ntbase = (n0 >> 3) + wn * 4;

    const uint32_t sX0 = smem_u32(sX);

    auto stage = [&](int c) {
#pragma unroll
        for (int r = 0; r < 2; r++) {
            const int idx = tid + r * 256;
            const int mat = idx >> 8, row = (idx >> 1) & 127, q = idx & 1;
            const char* src = (const char*)(mat ? g_Xl : g_Xh) +
                              (((size_t)(m0 + row) * 512 + c * 16) << 1) + q * 16;
            const uint32_t dst = sX0 + (c & 1) * 12288 + mat * 6144 + row * 48 + q * 16;
            CP16(dst, src);
        }
    };

    float d[4][4][4] = {};

    stage(0);
    asm volatile("cp.async.commit_group;" ::: "memory");

    for (int c = 0; c < 32; c++) {
        __syncthreads();
        if (c < 31) {
            stage(c + 1);
            asm volatile("cp.async.commit_group;" ::: "memory");
            asm volatile("cp.async.wait_group 1;" ::: "memory");
        } else {
            asm volatile("cp.async.wait_group 0;" ::: "memory");
        }
        __syncthreads();

        uint2 bh[4], bl[4];
#pragma unroll
        for (int nt = 0; nt < 4; nt++) {
            const size_t off = (((size_t)(ntbase + nt)) * 32 + c) * 32 + lane;
            bh[nt] = WX[off];
            bl[nt] = WX[off + MATSTRIDE];
        }

        const uint32_t slot = sX0 + (c & 1) * 12288;
        const uint32_t lrow = (lane & 15) * 48 + ((lane >> 4) << 4);
#pragma unroll
        for (int mt = 0; mt < 4; mt++) {
            const uint32_t arow = slot + (wm * 64 + mt * 16) * 48 + lrow;
            uint32_t a0, a1, a2, a3, l0, l1, l2, l3;
            LDSM_X4(a0, a1, a2, a3, arow);
            LDSM_X4(l0, l1, l2, l3, arow + 6144);
#pragma unroll
            for (int nt = 0; nt < 4; nt++) {
                MMA16816(d[mt][nt], a0, a1, a2, a3, bh[nt].x, bh[nt].y);
                MMA16816(d[mt][nt], a0, a1, a2, a3, bl[nt].x, bl[nt].y);
                MMA16816(d[mt][nt], l0, l1, l2, l3, bh[nt].x, bh[nt].y);
            }
        }
    }

    // Epilogue: add permuted bias, scatter to g_xz[dir][t][b][p]
#pragma unroll
    for (int mt = 0; mt < 4; mt++) {
#pragma unroll
        for (int nt = 0; nt < 4; nt++) {
            const int n = n0 + wn * 32 + nt * 8 + qc * 2;
            const float2 bv = *(const float2*)(g_biasp + dir * GG + n);
            const int ma = m0 + wm * 64 + mt * 16 + qr;
            const int mb = ma + 8;
            float2 v0, v1;
            v0.x = d[mt][nt][0] + bv.x; v0.y = d[mt][nt][1] + bv.y;
            v1.x = d[mt][nt][2] + bv.x; v1.y = d[mt][nt][3] + bv.y;
            *(float2*)(g_xz + (((size_t)dir * TT + (ma & 511)) * BB + (ma >> 9)) * GG + n) = v0;
            *(float2*)(g_xz + (((size_t)dir * TT + (mb & 511)) * BB + (mb >> 9)) * GG + n) = v1;
        }
    }
}

// ---------------------------------------------------------------------------
// Persistent recurrence: grid (64,2) CTAs x 512 threads, one launch for all
// 512 steps. 16 warps = 8 ntiles x 2 k-halves; k chunks of 64 (8 iters/step);
// software grid barrier between steps; c state lives in registers.
// ---------------------------------------------------------------------------
__global__ void __launch_bounds__(512, 1) lstm_kernel(float* __restrict__ out) {
    extern __shared__ char dsm[];
    // layout: [2 buf x 36864B]  (buf = 2kh x 2mat x 64 rows x 144B)
    //         sred (16KB) and sh (4.4KB) overlay buffer0 during epilogue.
    const uint32_t sA0 = smem_u32(dsm);
    float* sred = (float*)dsm;                     // [8nt][16][32]
    float (*sh)[17] = (float(*)[17])(dsm + 16384); // [64][17]

    const int dir  = blockIdx.y;
    const int nblk = blockIdx.x;
    const int tid  = threadIdx.x;
    const int warp = tid >> 5;
    const int lane = tid & 31;
    const int ntw = warp & 7;
    const int kh  = warp >> 3;
    const int qr = lane >> 2;
    const int qc = lane & 3;
    const int ntg = nblk * 8 + ntw;

    const uint2* Bh = g_Wfrag + (((size_t)(dir * 2 + 0) * 512 + ntg) * 64) * 32 + lane;
    const uint2* Bl = g_Wfrag + (((size_t)(dir * 2 + 1) * 512 + ntg) * 64) * 32 + lane;

    const int u = qc >> 1;
    const int j = nblk * 16 + ntw * 2 + u;
    const bool odd = qc & 1;
    const int lu = ntw * 2 + u;

    // stage indices (constant per thread)
    const int st_khs = tid >> 8;            // with r-offset below
    float cv[4] = {0.0f, 0.0f, 0.0f, 0.0f};

    for (int s = 0; s < TT; s++) {
        const int t  = dir ? (TT - 1 - s) : s;
        const int pr = s & 1;
        const int pw = pr ^ 1;
        const char* srcA = g_A + (size_t)(pr * 2 + dir) * 2 * A_MAT;

        // prefetch xz for this step (hidden under the mma loop)
        float4 xv[4];
        if (kh == 0) {
            const float* xz = g_xz + ((size_t)dir * TT + t) * BB * GG;
#pragma unroll
            for (int mt = 0; mt < 4; mt++) {
                const int b = mt * 16 + qr + (odd ? 8 : 0);
                xv[mt] = *(const float4*)(xz + (size_t)b * GG + j * 4);
            }
        }

        auto stage = [&](int c) {
#pragma unroll
            for (int r = 0; r < 4; r++) {
                const int idx = tid + r * 512;
                const int khs = idx >> 10;
                const int m = (idx >> 9) & 1;
                const int b = (idx >> 3) & 63;
                const int q = idx & 7;
                const char* src = srcA + (size_t)m * A_MAT +
                                  ((size_t)((khs * 8 + c) * 64 + b)) * 128 + q * 16;
                const uint32_t dst = sA0 + (c & 1) * 36864 + khs * 18432 +
                                     m * 9216 + b * 144 + q * 16;
                CP16(dst, src);
            }
        };

        float d[4][4] = {};

        stage(0);
        asm volatile("cp.async.commit_group;" ::: "memory");

        for (int c = 0; c < 8; c++) {
            // W fragments for this chunk (L2; land during stage wait)
            uint2 wh[4], wl[4];
#pragma unroll
            for (int sub = 0; sub < 4; sub++) {
                const size_t off = (size_t)((kh * 8 + c) * 4 + sub) * 32;
                wh[sub] = Bh[off];
                wl[sub] = Bl[off];
            }
            __syncthreads();
            if (c < 7) {
                stage(c + 1);
                asm volatile("cp.async.commit_group;" ::: "memory");
                asm volatile("cp.async.wait_group 1;" ::: "memory");
            } else {
                asm volatile("cp.async.wait_group 0;" ::: "memory");
            }
            __syncthreads();

            const uint32_t slot = sA0 + (c & 1) * 36864 + kh * 18432;
            const uint32_t lrow = (lane & 15) * 144 + ((lane >> 4) << 4);
#pragma unroll
            for (int sub = 0; sub < 4; sub++) {
                const uint32_t arow = slot + sub * 32 + lrow;
#pragma unroll
                for (int mt = 0; mt < 4; mt++) {
                    uint32_t a0, a1, a2, a3, l0, l1, l2, l3;
                    LDSM_X4(a0, a1, a2, a3, arow + mt * 2304);
                    LDSM_X4(l0, l1, l2, l3, arow + mt * 2304 + 9216);
                    MMA16816(d[mt], a0, a1, a2, a3, wh[sub].x, wh[sub].y);
                    MMA16816(d[mt], a0, a1, a2, a3, wl[sub].x, wl[sub].y);
                    MMA16816(d[mt], l0, l1, l2, l3, wh[sub].x, wh[sub].y);
                }
            }
        }

        // --- cross-k reduction (sred overlays buffer0; last chunk used buf1) ---
        if (kh == 1) {
#pragma unroll
            for (int mt = 0; mt < 4; mt++)
#pragma unroll
                for (int e = 0; e < 4; e++)
                    sred[(ntw * 16 + mt * 4 + e) * 32 + lane] = d[mt][e];
        }
        __syncthreads();

        if (kh == 0) {
#pragma unroll
            for (int mt = 0; mt < 4; mt++)
#pragma unroll
                for (int e = 0; e < 4; e++)
                    d[mt][e] += sred[(ntw * 16 + mt * 4 + e) * 32 + lane];

#pragma unroll
            for (int mt = 0; mt < 4; mt++) {
                float e0 = __shfl_xor_sync(0xffffffffu, d[mt][0], 1);
                float e1 = __shfl_xor_sync(0xffffffffu, d[mt][1], 1);
                float e2 = __shfl_xor_sync(0xffffffffu, d[mt][2], 1);
                float e3 = __shfl_xor_sync(0xffffffffu, d[mt][3], 1);
                const int b = mt * 16 + qr + (odd ? 8 : 0);

                float zi = odd ? e2 : d[mt][0];
                float zf = odd ? e3 : d[mt][1];
                float zo = odd ? d[mt][2] : e0;
                float zg = odd ? d[mt][3] : e1;

                zi += xv[mt].x; zf += xv[mt].y; zo += xv[mt].z; zg += xv[mt].w;

                const float ig = 1.0f / (1.0f + __expf(-zi));
                const float fg = 1.0f / (1.0f + __expf(-zf));
                const float og = 1.0f / (1.0f + __expf(-zo));
                const float gt = tanhf(zg);

                const float cn = fg * cv[mt] + ig * gt;
                const float hn = og * tanhf(cn);
                cv[mt] = cn;
                out[(((size_t)b * TT + t) * 2 + dir) * HH + j] = hn;
                sh[b][lu] = hn;
            }
        }
        __syncthreads();

        // --- write h (hi/lo fp16) for next step, parity pw ---
        if (tid < 128) {
            const int b = tid & 63;
            const int mat = tid >> 6;
            char* dst = g_A + ((size_t)(pw * 2 + dir) * 2 + mat) * A_MAT +
                        ((size_t)((nblk >> 2) * 64 + b)) * 128 + (nblk & 3) * 32;
            __half tmp[16];
#pragma unroll
            for (int q = 0; q < 16; q++) {
                float h = sh[b][q];
                __half hh = __float2half_rn(h);
                tmp[q] = mat ? __float2half_rn(h - __half2float(hh)) : hh;
            }
            *(uint4*)(dst)      = *(uint4*)(tmp);
            *(uint4*)(dst + 16) = *(uint4*)(tmp + 8);
            __threadfence();   // publish g_A before barrier arrive
        }

        // --- software grid barrier (skip after last step) ---
        if (s < TT - 1) {
            __syncthreads();
            if (tid == 0) {
                asm volatile("red.release.gpu.global.add.u32 [%0], 1;"
                             :: "l"(&g_barrier) : "memory");
                const unsigned target = 128u * (unsigned)(s + 1);
                unsigned v;
                do {
                    asm volatile("ld.acquire.gpu.global.u32 %0, [%1];"
                                 : "=r"(v) : "l"(&g_barrier) : "memory");
                } while (v < target);
            }
            __syncthreads();
        }
    }
}

// ---------------------------------------------------------------------------
// Launch
// ---------------------------------------------------------------------------
extern "C" void kernel_launch(void* const* d_in, const int* in_sizes, int n_in,
                              void* d_out, int out_size) {
    const float* X    = (const float*)d_in[0];
    const float* Wx_f = (const float*)d_in[1];
    const float* Wh_f = (const float*)d_in[2];
    const float* b_f  = (const float*)d_in[3];
    const float* Wx_b = (const float*)d_in[4];
    const float* Wh_b = (const float*)d_in[5];
    const float* b_b  = (const float*)d_in[6];
    float* out = (float*)d_out;

    cudaFuncSetAttribute(lstm_kernel,
                         cudaFuncAttributeMaxDynamicSharedMemorySize, 73728);

    init_kernel<<<1024, 256>>>();
    convX_kernel<<<16384, 256>>>(X);
    convW_kernel<<<8192, 256>>>(Wh_f, Wh_b);
    convWx_kernel<<<4096, 256>>>(Wx_f, Wx_b, b_f, b_b);

    proj_kernel<<<dim3(32, 256, 2), 256>>>();

    lstm_kernel<<<dim3(64, 2), 512, 73728>>>(out);
}